// round 13
// baseline (speedup 1.0000x reference)
#include <cuda_runtime.h>
#include <cuda_fp16.h>

typedef unsigned long long u64;
typedef unsigned int u32;

#define K_CODES 8192
#define EDIM 128
#define TM 128
#define TN 128
#define NCHUNK 2048               // codes per CTA
#define NT_LOCAL (NCHUNK / TN)    // 16 inner tiles
#define SAH 136                   // padded row stride (halfs)
#define SAW 68                    // row stride in 32-bit words
#define A_BYTES (128 * SAH * 2)   // 34816
#define STAGE_BYTES (128 * SAH * 2)
#define ZS_OFF (3 * A_BYTES)                 // float[128]
#define SB_OFF (ZS_OFF + 512)                // u64[128]
#define SMEM_TOTAL (120 * 1024)              // pin 1 CTA/SM
#define DELTA 3e-3f
#define N_ROWS 32768
#define N_RB (N_ROWS / TM)        // 256 row-blocks

__device__ float  d_esq[K_CODES];
__device__ __align__(16) u32 d_emb_h[K_CODES * 64];   // fp16 image of emb
__device__ int    d_counts[K_CODES];
__device__ u64    d_minkey[N_ROWS];
__device__ u64    d_cand[N_ROWS * 128];
__device__ u32    d_rbdone[N_RB];
__device__ double d_sumsq;
__device__ u32    d_rgdone;

// ---------------- helpers ----------------
__device__ __forceinline__ u32 smem_u32(const void* p) {
    u32 a; asm("{ .reg .u64 t; cvta.to.shared.u64 t, %1; cvt.u32.u64 %0, t; }" : "=r"(a) : "l"(p));
    return a;
}
__device__ __forceinline__ u32 fkey(float s) {
    u32 b = __float_as_uint(s);
    return (b & 0x80000000u) ? ~b : (b | 0x80000000u);
}
__device__ __forceinline__ float unfkey(u32 k) {
    u32 b = (k & 0x80000000u) ? (k & 0x7FFFFFFFu) : ~k;
    return __uint_as_float(b);
}
__device__ __forceinline__ void cp16(u32 dst, const void* src) {
    asm volatile("cp.async.cg.shared.global [%0], [%1], 16;" :: "r"(dst), "l"(src) : "memory");
}
__device__ __forceinline__ void mma16h(u32* c, const u32* a, const u32* b) {
    asm volatile(
        "mma.sync.aligned.m16n8k16.row.col.f16.f16.f16.f16 "
        "{%0,%1}, {%2,%3,%4,%5}, {%6,%7}, {%0,%1};"
        : "+r"(c[0]), "+r"(c[1])
        : "r"(a[0]), "r"(a[1]), "r"(a[2]), "r"(a[3]), "r"(b[0]), "r"(b[1]));
}
__device__ __forceinline__ void ldsm4(u32* r, u32 addr) {
    asm volatile("ldmatrix.sync.aligned.m8n8.x4.shared.b16 {%0,%1,%2,%3}, [%4];"
        : "=r"(r[0]), "=r"(r[1]), "=r"(r[2]), "=r"(r[3]) : "r"(addr));
}
__device__ __forceinline__ u32 h2u(float x, float y) {
    __half2 h = __floats2half2_rn(x, y);
    return *(u32*)&h;
}
__device__ __forceinline__ void top2(u64& b1, u64& b2, u64 k) {
    if (k < b1) { b2 = b1; b1 = k; }
    else if (k < b2) { b2 = k; }
}

// ---------- kernel 0: emb fp16 image + esq + zero state ----------
__global__ void k_init(const float* __restrict__ emb) {
    int idx = blockIdx.x * blockDim.x + threadIdx.x;  // 0..32767
    {
        int row = idx >> 2, part = idx & 3;
        const float4* src = (const float4*)(emb + (size_t)row * EDIM) + part * 8;
        u32* dst = d_emb_h + row * 64 + part * 16;
        float s = 0.f;
#pragma unroll
        for (int i = 0; i < 8; i++) {
            float4 v = src[i];
            s += v.x * v.x + v.y * v.y + v.z * v.z + v.w * v.w;
            dst[i * 2]     = h2u(v.x, v.y);
            dst[i * 2 + 1] = h2u(v.z, v.w);
        }
        s += __shfl_xor_sync(0xffffffffu, s, 1);
        s += __shfl_xor_sync(0xffffffffu, s, 2);
        if (part == 0) d_esq[row] = s;
    }
    if (idx < K_CODES) d_counts[idx] = 0;
    d_minkey[idx] = ~0ULL;
    if (idx < N_RB) d_rbdone[idx] = 0;
    if (idx == 0) { d_sumsq = 0.0; d_rgdone = 0; }
}

// epilogue of one (i,j) fragment pair (grid-exact formula, top-2)
#define EPI_PAIR(ACC, I, J) do {                                              \
    int _cg0 = colP + wn + (J) * 8 + 2 * lc;                                  \
    float2 _g0 = __half22float2(*(__half2*)&ACC[I][J][0]);                    \
    float2 _g1 = __half22float2(*(__half2*)&ACC[I][J][1]);                    \
    float _d0 = (zrow[I][0] + eqP[J][0]) - 2.f * _g0.x;                       \
    float _d1 = (zrow[I][0] + eqP[J][1]) - 2.f * _g0.y;                       \
    top2(best1[I][0], best2[I][0], ((u64)fkey(_d0) << 13) | (u32)_cg0);       \
    top2(best1[I][0], best2[I][0], ((u64)fkey(_d1) << 13) | (u32)(_cg0 + 1)); \
    float _e0 = (zrow[I][1] + eqP[J][0]) - 2.f * _g1.x;                       \
    float _e1 = (zrow[I][1] + eqP[J][1]) - 2.f * _g1.y;                       \
    top2(best1[I][1], best2[I][1], ((u64)fkey(_e0) << 13) | (u32)_cg0);       \
    top2(best1[I][1], best2[I][1], ((u64)fkey(_e1) << 13) | (u32)(_cg0 + 1)); \
} while (0)

// one tile: mma into ACC, interleaved epilogue chunks on ACCP (prev tile)
#define TILE_BODY(ACC, ACCP, TILE) do {                                       \
    const int colBase = colOrg + (TILE) * TN;                                 \
    float eqC[4][2];                                                          \
    _Pragma("unroll") for (int j = 0; j < 4; j++) {                           \
        int c0 = colBase + wn + j * 8 + 2 * lc;                               \
        eqC[j][0] = d_esq[c0]; eqC[j][1] = d_esq[c0 + 1];                     \
    }                                                                         \
    if ((TILE) + 1 < NT_LOCAL) {                                              \
        const u32* src = d_emb_h + (size_t)(colBase + TN) * 64;               \
        u32 dstb = bsOff + (((TILE) + 1) & 1) * STAGE_BYTES;                  \
        _Pragma("unroll") for (int i = 0; i < 8; i++) {                       \
            int idx = tid + i * 256; int r = idx >> 4, seg = idx & 15;        \
            cp16(dstb + (u32)(r * (SAH * 2) + seg * 16), src + r * 64 + seg * 4); \
        }                                                                     \
        asm volatile("cp.async.commit_group;" ::: "memory");                  \
        asm volatile("cp.async.wait_group 1;" ::: "memory");                  \
    } else {                                                                  \
        asm volatile("cp.async.wait_group 0;" ::: "memory");                  \
    }                                                                         \
    __syncthreads();                                                          \
    const u32 bSt = bsOff + ((TILE) & 1) * STAGE_BYTES;                       \
    _Pragma("unroll") for (int i = 0; i < 4; i++)                             \
        _Pragma("unroll") for (int j = 0; j < 4; j++) {                       \
            ACC[i][j][0] = 0u; ACC[i][j][1] = 0u;                             \
        }                                                                     \
    _Pragma("unroll") for (int kb = 0; kb < 8; kb++) {                        \
        const u32 kOff = (u32)kb * 32;                                        \
        u32 af[4][4], bf[2][4];                                               \
        _Pragma("unroll") for (int i = 0; i < 4; i++) ldsm4(af[i], aBase[i] + kOff); \
        _Pragma("unroll") for (int jj = 0; jj < 2; jj++) ldsm4(bf[jj], bSt + bBase[jj] + kOff); \
        _Pragma("unroll") for (int i = 0; i < 4; i++) {                       \
            mma16h(ACC[i][0], af[i], &bf[0][0]);                              \
            mma16h(ACC[i][1], af[i], &bf[0][2]);                              \
            mma16h(ACC[i][2], af[i], &bf[1][0]);                              \
            mma16h(ACC[i][3], af[i], &bf[1][2]);                              \
        }                                                                     \
        if (haveP) {                                                          \
            EPI_PAIR(ACCP, (kb >> 1), ((2 * kb) & 3));                        \
            EPI_PAIR(ACCP, (kb >> 1), ((2 * kb + 1) & 3));                    \
        }                                                                     \
    }                                                                         \
    _Pragma("unroll") for (int j = 0; j < 4; j++) {                           \
        eqP[j][0] = eqC[j][0]; eqP[j][1] = eqC[j][1];                         \
    }                                                                         \
    colP = colBase; haveP = true;                                             \
    __syncthreads();                                                          \
} while (0)

// ---------- main: fp16 screen + fused rescore/gather/finale ----------
extern "C" __global__ void __launch_bounds__(256, 1)
k_main(const float* __restrict__ z, const float* __restrict__ emb,
       float* __restrict__ out, int n_rows) {
    extern __shared__ char smem[];
    u32*   A32   = (u32*)smem;                        // [128][68] half2 words
    float* zsmem = (float*)(smem + ZS_OFF);           // [128]
    u64*   sbest = (u64*)(smem + SB_OFF);             // [128]
    __shared__ float s_red[8];
    __shared__ u32 s_flag, s_lastg;

    const int tid  = threadIdx.x;
    const int wid  = tid >> 5;
    const int lane = tid & 31;
    const int lr   = lane >> 2;
    const int lc   = lane & 3;
    const int wm   = (wid & 1) * 64;
    const int wn   = (wid >> 1) * 32;
    const int rb      = blockIdx.x >> 2;
    const int rowBase = rb * TM;
    const int nchunk  = blockIdx.x & 3;
    const int colOrg  = nchunk * NCHUNK;

    const u32 smb   = smem_u32(smem);
    const u32 bsOff = smb + A_BYTES;

    u32 aBase[4], bBase[2];
#pragma unroll
    for (int i = 0; i < 4; i++)
        aBase[i] = smb + ((u32)((wm + i * 16 + ((lane >> 3) & 1) * 8 + (lane & 7)) * SAW
                   + (lane >> 4) * 4)) * 4;
#pragma unroll
    for (int jj = 0; jj < 2; jj++)
        bBase[jj] = (u32)((wn + jj * 16 + ((lane >> 4) & 1) * 8 + (lane & 7)) * SAW
                   + ((lane >> 3) & 1) * 4) * 4;

    // prefetch first B tile (async), then do z prologue under it
    {
        const u32* srcB = d_emb_h + (size_t)colOrg * 64;
#pragma unroll
        for (int i = 0; i < 8; i++) {
            int idx = tid + i * 256;
            int r = idx >> 4, seg = idx & 15;
            cp16(bsOff + (u32)(r * (SAH * 2) + seg * 16), srcB + r * 64 + seg * 4);
        }
        asm volatile("cp.async.commit_group;" ::: "memory");
    }

    // prologue: zsq (exact, sequential order) + A fp16 conversion (hidden)
    if (tid < 128) {
        const float4* zr = (const float4*)(z + (size_t)(rowBase + tid) * EDIM);
        float s = 0.f;
#pragma unroll
        for (int q = 0; q < 32; q++) {
            float4 v = zr[q];
            s += v.x * v.x + v.y * v.y + v.z * v.z + v.w * v.w;
            A32[tid * SAW + q * 2]     = h2u(v.x, v.y);
            A32[tid * SAW + q * 2 + 1] = h2u(v.z, v.w);
        }
        zsmem[tid] = s;
        sbest[tid] = ~0ULL;
    }
    __syncthreads();

    float zrow[4][2];
#pragma unroll
    for (int i = 0; i < 4; i++) {
        zrow[i][0] = zsmem[wm + i * 16 + lr];
        zrow[i][1] = zsmem[wm + i * 16 + lr + 8];
    }

    u64 best1[4][2], best2[4][2];
#pragma unroll
    for (int i = 0; i < 4; i++)
#pragma unroll
        for (int s = 0; s < 2; s++) { best1[i][s] = ~0ULL; best2[i][s] = ~0ULL; }

    u32 accA[4][4][2], accB[4][4][2];
    float eqP[4][2];
    int colP = 0;
    bool haveP = false;

#pragma unroll 1
    for (int t2 = 0; t2 < NT_LOCAL / 2; t2++) {
        TILE_BODY(accA, accB, 2 * t2);
        TILE_BODY(accB, accA, 2 * t2 + 1);
    }
#pragma unroll
    for (int p = 0; p < 16; p++) EPI_PAIR(accB, (p >> 2), (p & 3));

    // candidates: this CTA owns 32 slots/row at offset nchunk*32
    const int slot = (wid >> 1) * 4 + lc;             // 0..15 per row
#pragma unroll
    for (int i = 0; i < 4; i++)
#pragma unroll
        for (int s = 0; s < 2; s++) {
            int rl = wm + i * 16 + lr + s * 8;
            atomicMin(&sbest[rl], best1[i][s]);
            u64* c = &d_cand[(size_t)(rowBase + rl) * 128 + nchunk * 32 + slot * 2];
            c[0] = best1[i][s];
            c[1] = best2[i][s];
        }
    __syncthreads();
    if (tid < 128) atomicMin(&d_minkey[rowBase + tid], sbest[tid]);

    // rendezvous: last CTA of this row-block rescores + gathers
    __threadfence();
    __syncthreads();
    if (tid == 0) s_flag = (atomicAdd(&d_rbdone[rb], 1u) == 3u) ? 1u : 0u;
    __syncthreads();
    if (!s_flag) return;
    __threadfence();

    float wsum = 0.f;
#pragma unroll 1
    for (int rr = 0; rr < 16; rr++) {
        const int rl = wid * 16 + rr;
        const int r  = rowBase + rl;
        u64 mk = d_minkey[r];
        float dmin = unfkey((u32)(mk >> 13));
        u32 thr = fkey(dmin + DELTA);

        u64 mykey = ~0ULL;
#pragma unroll
        for (int it = 0; it < 4; it++) {
            u64 key = d_cand[(size_t)r * 128 + lane + it * 32];
            if ((u32)(key >> 13) <= thr) {
                int idx = (int)(key & 0x1FFFULL);
                const float4* zr = (const float4*)(z + (size_t)r * EDIM);
                const float4* er = (const float4*)(emb + (size_t)idx * EDIM);
                float dot = 0.f;
#pragma unroll
                for (int q = 0; q < 32; q++) {
                    float4 a = zr[q], b = er[q];
                    dot += a.x * b.x + a.y * b.y + a.z * b.z + a.w * b.w;
                }
                float tt = zsmem[rl] + d_esq[idx];    // fl(zsq+esq)
                float d = tt - 2.f * dot;             // fl(t - 2*dot): grid-exact
                u64 k2 = ((u64)fkey(d) << 13) | (u32)idx;
                if (k2 < mykey) mykey = k2;
            }
        }
#pragma unroll
        for (int off = 16; off; off >>= 1) {
            u64 o = __shfl_xor_sync(0xffffffffu, mykey, off);
            if (o < mykey) mykey = o;
        }
        const int idx = (int)(mykey & 0x1FFFULL);

        float4 q  = ((const float4*)(emb + (size_t)idx * EDIM))[lane];
        float4 zz = ((const float4*)(z   + (size_t)r   * EDIM))[lane];
        float4 o4;
        float s = 0.f, df;
        df = q.x - zz.x; o4.x = zz.x + df; s += df * df;
        df = q.y - zz.y; o4.y = zz.y + df; s += df * df;
        df = q.z - zz.z; o4.z = zz.z + df; s += df * df;
        df = q.w - zz.w; o4.w = zz.w + df; s += df * df;
        ((float4*)(out + (size_t)r * EDIM))[lane] = o4;
#pragma unroll
        for (int off = 16; off; off >>= 1) s += __shfl_xor_sync(0xffffffffu, s, off);
        if (lane == 0) {
            atomicAdd(&d_counts[idx], 1);
            wsum += s;
        }
    }
    if (lane == 0) s_red[wid] = wsum;
    __syncthreads();
    if (tid == 0) {
        float bs = 0.f;
#pragma unroll
        for (int i = 0; i < 8; i++) bs += s_red[i];
        atomicAdd(&d_sumsq, (double)bs);
        __threadfence();
        s_lastg = (atomicAdd(&d_rgdone, 1u) == (u32)N_RB - 1u) ? 1u : 0u;
    }
    __syncthreads();

    if (s_lastg) {
        __threadfence();
        float acc = 0.f;
        float invN = 1.f / (float)n_rows;
        for (int k = tid; k < K_CODES; k += 256) {
            float e = (float)d_counts[k] * invN;
            acc += e * logf(e + 1e-8f);
        }
#pragma unroll
        for (int off = 16; off; off >>= 1) acc += __shfl_xor_sync(0xffffffffu, acc, off);
        if (lane == 0) s_red[wid] = acc;
        __syncthreads();
        if (tid == 0) {
            float t = 0.f;
#pragma unroll
            for (int i = 0; i < 8; i++) t += s_red[i];
            double ss = atomicAdd(&d_sumsq, 0.0);
            float m = (float)(ss / (double)((size_t)n_rows * EDIM));
            out[(size_t)n_rows * EDIM]     = 0.25f * m + m;
            out[(size_t)n_rows * EDIM + 1] = expf(-t);
        }
    }
}

extern "C" void kernel_launch(void* const* d_in, const int* in_sizes, int n_in,
                              void* d_out, int out_size) {
    const float* z   = (const float*)d_in[0];
    const float* emb = (const float*)d_in[1];
    float* out = (float*)d_out;
    int n_rows = in_sizes[0] / EDIM;                  // 32768

    cudaFuncSetAttribute(k_main, cudaFuncAttributeMaxDynamicSharedMemorySize, SMEM_TOTAL);

    k_init<<<128, 256>>>(emb);
    k_main<<<(n_rows / TM) * 4, 256, SMEM_TOTAL>>>(z, emb, out, n_rows);
}

// round 14
// speedup vs baseline: 1.0788x; 1.0788x over previous
#include <cuda_runtime.h>
#include <cuda_fp16.h>

typedef unsigned long long u64;
typedef unsigned int u32;

#define K_CODES 8192
#define EDIM 128
#define TM 128
#define TN 128
#define NCHUNK 2048               // codes per CTA
#define NT_LOCAL (NCHUNK / TN)    // 16 inner tiles
#define SAH 136                   // padded row stride (halfs)
#define SAW 68                    // row stride in 32-bit words
#define A_BYTES (128 * SAH * 2)   // 34816
#define STAGE_BYTES (128 * SAH * 2)
#define ZS_OFF (3 * A_BYTES)                 // float[128]
#define SB_OFF (ZS_OFF + 512)                // u64[128]
#define SMEM_TOTAL (120 * 1024)              // pin 1 CTA/SM
#define DELTA 3e-3f
#define N_ROWS 32768

__device__ float  d_esq[K_CODES];
__device__ float  d_zsq[N_ROWS];
__device__ __align__(16) u32 d_emb_h[K_CODES * 64];   // fp16 image of emb
__device__ int    d_counts[K_CODES];
__device__ u64    d_minkey[N_ROWS];
__device__ u64    d_cand[N_ROWS * 128];
__device__ double d_sumsq;
__device__ u32    d_rgdone;

// ---------------- helpers ----------------
__device__ __forceinline__ u32 smem_u32(const void* p) {
    u32 a; asm("{ .reg .u64 t; cvta.to.shared.u64 t, %1; cvt.u32.u64 %0, t; }" : "=r"(a) : "l"(p));
    return a;
}
__device__ __forceinline__ u32 fkey(float s) {
    u32 b = __float_as_uint(s);
    return (b & 0x80000000u) ? ~b : (b | 0x80000000u);
}
__device__ __forceinline__ float unfkey(u32 k) {
    u32 b = (k & 0x80000000u) ? (k & 0x7FFFFFFFu) : ~k;
    return __uint_as_float(b);
}
__device__ __forceinline__ void cp16(u32 dst, const void* src) {
    asm volatile("cp.async.cg.shared.global [%0], [%1], 16;" :: "r"(dst), "l"(src) : "memory");
}
__device__ __forceinline__ void mma16h(u32* c, const u32* a, const u32* b) {
    asm volatile(
        "mma.sync.aligned.m16n8k16.row.col.f16.f16.f16.f16 "
        "{%0,%1}, {%2,%3,%4,%5}, {%6,%7}, {%0,%1};"
        : "+r"(c[0]), "+r"(c[1])
        : "r"(a[0]), "r"(a[1]), "r"(a[2]), "r"(a[3]), "r"(b[0]), "r"(b[1]));
}
__device__ __forceinline__ void ldsm4(u32* r, u32 addr) {
    asm volatile("ldmatrix.sync.aligned.m8n8.x4.shared.b16 {%0,%1,%2,%3}, [%4];"
        : "=r"(r[0]), "=r"(r[1]), "=r"(r[2]), "=r"(r[3]) : "r"(addr));
}
__device__ __forceinline__ u32 h2u(float x, float y) {
    __half2 h = __floats2half2_rn(x, y);
    return *(u32*)&h;
}
__device__ __forceinline__ void top2(u64& b1, u64& b2, u64 k) {
    if (k < b1) { b2 = b1; b1 = k; }
    else if (k < b2) { b2 = k; }
}

// ---------- kernel 0: emb fp16 image + esq + zero state ----------
__global__ void k_init(const float* __restrict__ emb) {
    int idx = blockIdx.x * blockDim.x + threadIdx.x;  // 0..32767
    {
        int row = idx >> 2, part = idx & 3;
        const float4* src = (const float4*)(emb + (size_t)row * EDIM) + part * 8;
        u32* dst = d_emb_h + row * 64 + part * 16;
        float s = 0.f;
#pragma unroll
        for (int i = 0; i < 8; i++) {
            float4 v = src[i];
            s += v.x * v.x + v.y * v.y + v.z * v.z + v.w * v.w;
            dst[i * 2]     = h2u(v.x, v.y);
            dst[i * 2 + 1] = h2u(v.z, v.w);
        }
        s += __shfl_xor_sync(0xffffffffu, s, 1);
        s += __shfl_xor_sync(0xffffffffu, s, 2);
        if (part == 0) d_esq[row] = s;
    }
    if (idx < K_CODES) d_counts[idx] = 0;
    d_minkey[idx] = ~0ULL;
    if (idx == 0) { d_sumsq = 0.0; d_rgdone = 0; }
}

// epilogue of one (i,j) fragment pair (grid-exact formula, top-2)
#define EPI_PAIR(ACC, I, J) do {                                              \
    int _cg0 = colP + wn + (J) * 8 + 2 * lc;                                  \
    float2 _g0 = __half22float2(*(__half2*)&ACC[I][J][0]);                    \
    float2 _g1 = __half22float2(*(__half2*)&ACC[I][J][1]);                    \
    float _d0 = (zrow[I][0] + eqP[J][0]) - 2.f * _g0.x;                       \
    float _d1 = (zrow[I][0] + eqP[J][1]) - 2.f * _g0.y;                       \
    top2(best1[I][0], best2[I][0], ((u64)fkey(_d0) << 13) | (u32)_cg0);       \
    top2(best1[I][0], best2[I][0], ((u64)fkey(_d1) << 13) | (u32)(_cg0 + 1)); \
    float _e0 = (zrow[I][1] + eqP[J][0]) - 2.f * _g1.x;                       \
    float _e1 = (zrow[I][1] + eqP[J][1]) - 2.f * _g1.y;                       \
    top2(best1[I][1], best2[I][1], ((u64)fkey(_e0) << 13) | (u32)_cg0);       \
    top2(best1[I][1], best2[I][1], ((u64)fkey(_e1) << 13) | (u32)(_cg0 + 1)); \
} while (0)

// one tile: mma into ACC, interleaved epilogue chunks on ACCP (prev tile)
#define TILE_BODY(ACC, ACCP, TILE) do {                                       \
    const int colBase = colOrg + (TILE) * TN;                                 \
    float eqC[4][2];                                                          \
    _Pragma("unroll") for (int j = 0; j < 4; j++) {                           \
        int c0 = colBase + wn + j * 8 + 2 * lc;                               \
        eqC[j][0] = d_esq[c0]; eqC[j][1] = d_esq[c0 + 1];                     \
    }                                                                         \
    if ((TILE) + 1 < NT_LOCAL) {                                              \
        const u32* src = d_emb_h + (size_t)(colBase + TN) * 64;               \
        u32 dstb = bsOff + (((TILE) + 1) & 1) * STAGE_BYTES;                  \
        _Pragma("unroll") for (int i = 0; i < 8; i++) {                       \
            int idx = tid + i * 256; int r = idx >> 4, seg = idx & 15;        \
            cp16(dstb + (u32)(r * (SAH * 2) + seg * 16), src + r * 64 + seg * 4); \
        }                                                                     \
        asm volatile("cp.async.commit_group;" ::: "memory");                  \
        asm volatile("cp.async.wait_group 1;" ::: "memory");                  \
    } else {                                                                  \
        asm volatile("cp.async.wait_group 0;" ::: "memory");                  \
    }                                                                         \
    __syncthreads();                                                          \
    const u32 bSt = bsOff + ((TILE) & 1) * STAGE_BYTES;                       \
    _Pragma("unroll") for (int i = 0; i < 4; i++)                             \
        _Pragma("unroll") for (int j = 0; j < 4; j++) {                       \
            ACC[i][j][0] = 0u; ACC[i][j][1] = 0u;                             \
        }                                                                     \
    _Pragma("unroll") for (int kb = 0; kb < 8; kb++) {                        \
        const u32 kOff = (u32)kb * 32;                                        \
        u32 af[4][4], bf[2][4];                                               \
        _Pragma("unroll") for (int i = 0; i < 4; i++) ldsm4(af[i], aBase[i] + kOff); \
        _Pragma("unroll") for (int jj = 0; jj < 2; jj++) ldsm4(bf[jj], bSt + bBase[jj] + kOff); \
        _Pragma("unroll") for (int i = 0; i < 4; i++) {                       \
            mma16h(ACC[i][0], af[i], &bf[0][0]);                              \
            mma16h(ACC[i][1], af[i], &bf[0][2]);                              \
            mma16h(ACC[i][2], af[i], &bf[1][0]);                              \
            mma16h(ACC[i][3], af[i], &bf[1][2]);                              \
        }                                                                     \
        if (haveP) {                                                          \
            EPI_PAIR(ACCP, (kb >> 1), ((2 * kb) & 3));                        \
            EPI_PAIR(ACCP, (kb >> 1), ((2 * kb + 1) & 3));                    \
        }                                                                     \
    }                                                                         \
    _Pragma("unroll") for (int j = 0; j < 4; j++) {                           \
        eqP[j][0] = eqC[j][0]; eqP[j][1] = eqC[j][1];                         \
    }                                                                         \
    colP = colBase; haveP = true;                                             \
    __syncthreads();                                                          \
} while (0)

// ---------- main: fp16 screening GEMM, N-split x4, pipelined epilogue ----------
extern "C" __global__ void __launch_bounds__(256, 1)
k_main(const float* __restrict__ z, const float* __restrict__ emb) {
    extern __shared__ char smem[];
    u32*   A32   = (u32*)smem;                        // [128][68] half2 words
    float* zsmem = (float*)(smem + ZS_OFF);           // [128]
    u64*   sbest = (u64*)(smem + SB_OFF);             // [128]

    const int tid  = threadIdx.x;
    const int wid  = tid >> 5;
    const int lane = tid & 31;
    const int lr   = lane >> 2;
    const int lc   = lane & 3;
    const int wm   = (wid & 1) * 64;
    const int wn   = (wid >> 1) * 32;
    const int rowBase = (blockIdx.x >> 2) * TM;
    const int nchunk  = blockIdx.x & 3;
    const int colOrg  = nchunk * NCHUNK;

    const u32 smb   = smem_u32(smem);
    const u32 bsOff = smb + A_BYTES;

    u32 aBase[4], bBase[2];
#pragma unroll
    for (int i = 0; i < 4; i++)
        aBase[i] = smb + ((u32)((wm + i * 16 + ((lane >> 3) & 1) * 8 + (lane & 7)) * SAW
                   + (lane >> 4) * 4)) * 4;
#pragma unroll
    for (int jj = 0; jj < 2; jj++)
        bBase[jj] = (u32)((wn + jj * 16 + ((lane >> 4) & 1) * 8 + (lane & 7)) * SAW
                   + ((lane >> 3) & 1) * 4) * 4;

    // prefetch first B tile (async); z prologue hides under it
    {
        const u32* srcB = d_emb_h + (size_t)colOrg * 64;
#pragma unroll
        for (int i = 0; i < 8; i++) {
            int idx = tid + i * 256;
            int r = idx >> 4, seg = idx & 15;
            cp16(bsOff + (u32)(r * (SAH * 2) + seg * 16), srcB + r * 64 + seg * 4);
        }
        asm volatile("cp.async.commit_group;" ::: "memory");
    }

    // prologue: zsq (exact, sequential order) + A fp16 conversion
    if (tid < 128) {
        const float4* zr = (const float4*)(z + (size_t)(rowBase + tid) * EDIM);
        float s = 0.f;
#pragma unroll
        for (int q = 0; q < 32; q++) {
            float4 v = zr[q];
            s += v.x * v.x + v.y * v.y + v.z * v.z + v.w * v.w;
            A32[tid * SAW + q * 2]     = h2u(v.x, v.y);
            A32[tid * SAW + q * 2 + 1] = h2u(v.z, v.w);
        }
        zsmem[tid] = s;
        sbest[tid] = ~0ULL;
        if (nchunk == 0) d_zsq[rowBase + tid] = s;    // for k_rg
    }
    __syncthreads();

    float zrow[4][2];
#pragma unroll
    for (int i = 0; i < 4; i++) {
        zrow[i][0] = zsmem[wm + i * 16 + lr];
        zrow[i][1] = zsmem[wm + i * 16 + lr + 8];
    }

    u64 best1[4][2], best2[4][2];
#pragma unroll
    for (int i = 0; i < 4; i++)
#pragma unroll
        for (int s = 0; s < 2; s++) { best1[i][s] = ~0ULL; best2[i][s] = ~0ULL; }

    u32 accA[4][4][2], accB[4][4][2];
    float eqP[4][2];
    int colP = 0;
    bool haveP = false;

#pragma unroll 1
    for (int t2 = 0; t2 < NT_LOCAL / 2; t2++) {
        TILE_BODY(accA, accB, 2 * t2);
        TILE_BODY(accB, accA, 2 * t2 + 1);
    }
#pragma unroll
    for (int p = 0; p < 16; p++) EPI_PAIR(accB, (p >> 2), (p & 3));

    // candidates: this CTA owns 32 slots/row at offset nchunk*32
    const int slot = (wid >> 1) * 4 + lc;             // 0..15 per row
#pragma unroll
    for (int i = 0; i < 4; i++)
#pragma unroll
        for (int s = 0; s < 2; s++) {
            int rl = wm + i * 16 + lr + s * 8;
            atomicMin(&sbest[rl], best1[i][s]);
            u64* c = &d_cand[(size_t)(rowBase + rl) * 128 + nchunk * 32 + slot * 2];
            c[0] = best1[i][s];
            c[1] = best2[i][s];
        }
    __syncthreads();
    if (tid < 128) atomicMin(&d_minkey[rowBase + tid], sbest[tid]);
}

// ---------- fused rescore + gather + sums + counts + finale ----------
__global__ void k_rg(const float* __restrict__ z, const float* __restrict__ emb,
                     float* __restrict__ out, int n_rows) {
    __shared__ float red[8];
    __shared__ u32 s_last;
    const int w = threadIdx.x >> 5;
    const int lane = threadIdx.x & 31;
    const int r = blockIdx.x * 8 + w;

    u64 mk = d_minkey[r];
    float dmin = unfkey((u32)(mk >> 13));
    u32 thr = fkey(dmin + DELTA);

    u64 mykey = ~0ULL;
#pragma unroll
    for (int it = 0; it < 4; it++) {
        u64 key = d_cand[(size_t)r * 128 + lane + it * 32];
        if ((u32)(key >> 13) <= thr) {
            int idx = (int)(key & 0x1FFFULL);
            const float4* zr = (const float4*)(z + (size_t)r * EDIM);
            const float4* er = (const float4*)(emb + (size_t)idx * EDIM);
            float dot = 0.f;
#pragma unroll
            for (int q = 0; q < 32; q++) {
                float4 a = zr[q], b = er[q];
                dot += a.x * b.x + a.y * b.y + a.z * b.z + a.w * b.w;
            }
            float tt = d_zsq[r] + d_esq[idx];         // fl(zsq+esq)
            float d = tt - 2.f * dot;                 // fl(t - 2*dot): grid-exact
            u64 k2 = ((u64)fkey(d) << 13) | (u32)idx;
            if (k2 < mykey) mykey = k2;
        }
    }
#pragma unroll
    for (int off = 16; off; off >>= 1) {
        u64 o = __shfl_xor_sync(0xffffffffu, mykey, off);
        if (o < mykey) mykey = o;
    }
    const int idx = (int)(mykey & 0x1FFFULL);

    float4 q  = ((const float4*)(emb + (size_t)idx * EDIM))[lane];
    float4 zz = ((const float4*)(z   + (size_t)r   * EDIM))[lane];
    float4 o4;
    float s = 0.f, df;
    df = q.x - zz.x; o4.x = zz.x + df; s += df * df;
    df = q.y - zz.y; o4.y = zz.y + df; s += df * df;
    df = q.z - zz.z; o4.z = zz.z + df; s += df * df;
    df = q.w - zz.w; o4.w = zz.w + df; s += df * df;
    ((float4*)(out + (size_t)r * EDIM))[lane] = o4;
#pragma unroll
    for (int off = 16; off; off >>= 1) s += __shfl_xor_sync(0xffffffffu, s, off);
    if (lane == 0) {
        atomicAdd(&d_counts[idx], 1);
        red[w] = s;
    }
    __syncthreads();
    if (threadIdx.x == 0) {
        float bs = 0.f;
#pragma unroll
        for (int i = 0; i < 8; i++) bs += red[i];
        atomicAdd(&d_sumsq, (double)bs);
        __threadfence();
        s_last = (atomicAdd(&d_rgdone, 1u) == gridDim.x - 1u) ? 1u : 0u;
    }
    __syncthreads();

    if (s_last) {
        __threadfence();
        float acc = 0.f;
        float invN = 1.f / (float)n_rows;
        for (int k = threadIdx.x; k < K_CODES; k += 256) {
            float e = (float)d_counts[k] * invN;
            acc += e * logf(e + 1e-8f);
        }
#pragma unroll
        for (int off = 16; off; off >>= 1) acc += __shfl_xor_sync(0xffffffffu, acc, off);
        if (lane == 0) red[w] = acc;
        __syncthreads();
        if (threadIdx.x == 0) {
            float t = 0.f;
#pragma unroll
            for (int i = 0; i < 8; i++) t += red[i];
            double ss = atomicAdd(&d_sumsq, 0.0);
            float m = (float)(ss / (double)((size_t)n_rows * EDIM));
            out[(size_t)n_rows * EDIM]     = 0.25f * m + m;
            out[(size_t)n_rows * EDIM + 1] = expf(-t);
        }
    }
}

extern "C" void kernel_launch(void* const* d_in, const int* in_sizes, int n_in,
                              void* d_out, int out_size) {
    const float* z   = (const float*)d_in[0];
    const float* emb = (const float*)d_in[1];
    float* out = (float*)d_out;
    int n_rows = in_sizes[0] / EDIM;                  // 32768

    cudaFuncSetAttribute(k_main, cudaFuncAttributeMaxDynamicSharedMemorySize, SMEM_TOTAL);

    k_init<<<128, 256>>>(emb);
    k_main<<<(n_rows / TM) * 4, 256, SMEM_TOTAL>>>(z, emb);
    k_rg<<<n_rows / 8, 256>>>(z, emb, out, n_rows);
}

// round 15
// speedup vs baseline: 1.1070x; 1.0261x over previous
#include <cuda_runtime.h>
#include <cuda_fp16.h>

typedef unsigned long long u64;
typedef unsigned int u32;

#define K_CODES 8192
#define EDIM 128
#define TM 128
#define TN 128
#define NCHUNK 2048               // codes per CTA
#define NT_LOCAL (NCHUNK / TN)    // 16 inner tiles
#define SAH 136                   // padded row stride (halfs)
#define SAW 68                    // row stride in 32-bit words
#define A_BYTES (128 * SAH * 2)   // 34816
#define STAGE_BYTES (128 * SAH * 2)
#define ZS_OFF (3 * A_BYTES)                 // float[128]
#define SB_OFF (ZS_OFF + 512)                // u64[128]
#define SMEM_TOTAL (120 * 1024)              // pin 1 CTA/SM
#define DELTA 3e-3f
#define N_ROWS 32768

__device__ float  d_esq[K_CODES];
__device__ float  d_zsq[N_ROWS];
__device__ __align__(16) u32 d_emb_h[K_CODES * 64];   // fp16 image of emb
__device__ __align__(16) u32 d_z_h[N_ROWS * 64];      // fp16 image of z
__device__ int    d_counts[K_CODES];
__device__ u64    d_minkey[N_ROWS];
__device__ u64    d_cand[N_ROWS * 128];
__device__ double d_sumsq;
__device__ u32    d_rgdone;

// ---------------- helpers ----------------
__device__ __forceinline__ u32 smem_u32(const void* p) {
    u32 a; asm("{ .reg .u64 t; cvta.to.shared.u64 t, %1; cvt.u32.u64 %0, t; }" : "=r"(a) : "l"(p));
    return a;
}
__device__ __forceinline__ u32 fkey(float s) {
    u32 b = __float_as_uint(s);
    return (b & 0x80000000u) ? ~b : (b | 0x80000000u);
}
__device__ __forceinline__ float unfkey(u32 k) {
    u32 b = (k & 0x80000000u) ? (k & 0x7FFFFFFFu) : ~k;
    return __uint_as_float(b);
}
__device__ __forceinline__ void cp16(u32 dst, const void* src) {
    asm volatile("cp.async.cg.shared.global [%0], [%1], 16;" :: "r"(dst), "l"(src) : "memory");
}
__device__ __forceinline__ void mma16h(u32* c, const u32* a, const u32* b) {
    asm volatile(
        "mma.sync.aligned.m16n8k16.row.col.f16.f16.f16.f16 "
        "{%0,%1}, {%2,%3,%4,%5}, {%6,%7}, {%0,%1};"
        : "+r"(c[0]), "+r"(c[1])
        : "r"(a[0]), "r"(a[1]), "r"(a[2]), "r"(a[3]), "r"(b[0]), "r"(b[1]));
}
__device__ __forceinline__ void ldsm4(u32* r, u32 addr) {
    asm volatile("ldmatrix.sync.aligned.m8n8.x4.shared.b16 {%0,%1,%2,%3}, [%4];"
        : "=r"(r[0]), "=r"(r[1]), "=r"(r[2]), "=r"(r[3]) : "r"(addr));
}
__device__ __forceinline__ u32 h2u(float x, float y) {
    __half2 h = __floats2half2_rn(x, y);
    return *(u32*)&h;
}
__device__ __forceinline__ void top2(u64& b1, u64& b2, u64 k) {
    if (k < b1) { b2 = b1; b1 = k; }
    else if (k < b2) { b2 = k; }
}

// ---------- kernel 0: fp16 images + zsq/esq (8 threads/row) ----------
__global__ void k_init(const float* __restrict__ z, const float* __restrict__ emb) {
    int idx = blockIdx.x * blockDim.x + threadIdx.x;  // 0..327679
    if (idx < 262144) {                               // z: 32768 rows x 8 threads
        int row = idx >> 3, part = idx & 7;
        const float4* src = (const float4*)(z + (size_t)row * EDIM) + part * 4;
        u32* dst = d_z_h + row * 64 + part * 8;
        float s = 0.f;
#pragma unroll
        for (int i = 0; i < 4; i++) {
            float4 v = src[i];
            s += v.x * v.x + v.y * v.y + v.z * v.z + v.w * v.w;
            dst[i * 2]     = h2u(v.x, v.y);
            dst[i * 2 + 1] = h2u(v.z, v.w);
        }
        s += __shfl_xor_sync(0xffffffffu, s, 1);
        s += __shfl_xor_sync(0xffffffffu, s, 2);
        s += __shfl_xor_sync(0xffffffffu, s, 4);
        if (part == 0) { d_zsq[row] = s; d_minkey[row] = ~0ULL; }
    } else {                                          // emb: 8192 rows x 8 threads
        int e = idx - 262144;
        int row = e >> 3, part = e & 7;
        const float4* src = (const float4*)(emb + (size_t)row * EDIM) + part * 4;
        u32* dst = d_emb_h + row * 64 + part * 8;
        float s = 0.f;
#pragma unroll
        for (int i = 0; i < 4; i++) {
            float4 v = src[i];
            s += v.x * v.x + v.y * v.y + v.z * v.z + v.w * v.w;
            dst[i * 2]     = h2u(v.x, v.y);
            dst[i * 2 + 1] = h2u(v.z, v.w);
        }
        s += __shfl_xor_sync(0xffffffffu, s, 1);
        s += __shfl_xor_sync(0xffffffffu, s, 2);
        s += __shfl_xor_sync(0xffffffffu, s, 4);
        if (part == 0) { d_esq[row] = s; d_counts[row] = 0; }
    }
    if (idx == 0) { d_sumsq = 0.0; d_rgdone = 0; }
}

// epilogue of one (i,j) fragment pair (grid-exact formula, top-2)
#define EPI_PAIR(ACC, I, J) do {                                              \
    int _cg0 = colP + wn + (J) * 8 + 2 * lc;                                  \
    float2 _g0 = __half22float2(*(__half2*)&ACC[I][J][0]);                    \
    float2 _g1 = __half22float2(*(__half2*)&ACC[I][J][1]);                    \
    float _d0 = (zrow[I][0] + eqP[J][0]) - 2.f * _g0.x;                       \
    float _d1 = (zrow[I][0] + eqP[J][1]) - 2.f * _g0.y;                       \
    top2(best1[I][0], best2[I][0], ((u64)fkey(_d0) << 13) | (u32)_cg0);       \
    top2(best1[I][0], best2[I][0], ((u64)fkey(_d1) << 13) | (u32)(_cg0 + 1)); \
    float _e0 = (zrow[I][1] + eqP[J][0]) - 2.f * _g1.x;                       \
    float _e1 = (zrow[I][1] + eqP[J][1]) - 2.f * _g1.y;                       \
    top2(best1[I][1], best2[I][1], ((u64)fkey(_e0) << 13) | (u32)_cg0);       \
    top2(best1[I][1], best2[I][1], ((u64)fkey(_e1) << 13) | (u32)(_cg0 + 1)); \
} while (0)

// one tile: mma into ACC, interleaved epilogue chunks on ACCP (prev tile)
#define TILE_BODY(ACC, ACCP, TILE) do {                                       \
    const int colBase = colOrg + (TILE) * TN;                                 \
    float eqC[4][2];                                                          \
    _Pragma("unroll") for (int j = 0; j < 4; j++) {                           \
        int c0 = colBase + wn + j * 8 + 2 * lc;                               \
        eqC[j][0] = d_esq[c0]; eqC[j][1] = d_esq[c0 + 1];                     \
    }                                                                         \
    if ((TILE) + 1 < NT_LOCAL) {                                              \
        const u32* src = d_emb_h + (size_t)(colBase + TN) * 64;               \
        u32 dstb = bsOff + (((TILE) + 1) & 1) * STAGE_BYTES;                  \
        _Pragma("unroll") for (int i = 0; i < 8; i++) {                       \
            int idx = tid + i * 256; int r = idx >> 4, seg = idx & 15;        \
            cp16(dstb + (u32)(r * (SAH * 2) + seg * 16), src + r * 64 + seg * 4); \
        }                                                                     \
        asm volatile("cp.async.commit_group;" ::: "memory");                  \
        asm volatile("cp.async.wait_group 1;" ::: "memory");                  \
    } else {                                                                  \
        asm volatile("cp.async.wait_group 0;" ::: "memory");                  \
    }                                                                         \
    __syncthreads();                                                          \
    const u32 bSt = bsOff + ((TILE) & 1) * STAGE_BYTES;                       \
    _Pragma("unroll") for (int i = 0; i < 4; i++)                             \
        _Pragma("unroll") for (int j = 0; j < 4; j++) {                       \
            ACC[i][j][0] = 0u; ACC[i][j][1] = 0u;                             \
        }                                                                     \
    _Pragma("unroll") for (int kb = 0; kb < 8; kb++) {                        \
        const u32 kOff = (u32)kb * 32;                                        \
        u32 af[4][4], bf[2][4];                                               \
        _Pragma("unroll") for (int i = 0; i < 4; i++) ldsm4(af[i], aBase[i] + kOff); \
        _Pragma("unroll") for (int jj = 0; jj < 2; jj++) ldsm4(bf[jj], bSt + bBase[jj] + kOff); \
        _Pragma("unroll") for (int i = 0; i < 4; i++) {                       \
            mma16h(ACC[i][0], af[i], &bf[0][0]);                              \
            mma16h(ACC[i][1], af[i], &bf[0][2]);                              \
            mma16h(ACC[i][2], af[i], &bf[1][0]);                              \
            mma16h(ACC[i][3], af[i], &bf[1][2]);                              \
        }                                                                     \
        if (haveP) {                                                          \
            EPI_PAIR(ACCP, (kb >> 1), ((2 * kb) & 3));                        \
            EPI_PAIR(ACCP, (kb >> 1), ((2 * kb + 1) & 3));                    \
        }                                                                     \
    }                                                                         \
    _Pragma("unroll") for (int j = 0; j < 4; j++) {                           \
        eqP[j][0] = eqC[j][0]; eqP[j][1] = eqC[j][1];                         \
    }                                                                         \
    colP = colBase; haveP = true;                                             \
    __syncthreads();                                                          \
} while (0)

// ---------- main: fp16 screening GEMM, N-split x4, pipelined epilogue ----------
extern "C" __global__ void __launch_bounds__(256, 1)
k_main(const float* __restrict__ z, const float* __restrict__ emb) {
    extern __shared__ char smem[];
    float* zsmem = (float*)(smem + ZS_OFF);           // [128]
    u64*   sbest = (u64*)(smem + SB_OFF);             // [128]

    const int tid  = threadIdx.x;
    const int wid  = tid >> 5;
    const int lane = tid & 31;
    const int lr   = lane >> 2;
    const int lc   = lane & 3;
    const int wm   = (wid & 1) * 64;
    const int wn   = (wid >> 1) * 32;
    const int rowBase = (blockIdx.x >> 2) * TM;
    const int nchunk  = blockIdx.x & 3;
    const int colOrg  = nchunk * NCHUNK;

    const u32 smb   = smem_u32(smem);
    const u32 bsOff = smb + A_BYTES;

    u32 aBase[4], bBase[2];
#pragma unroll
    for (int i = 0; i < 4; i++)
        aBase[i] = smb + ((u32)((wm + i * 16 + ((lane >> 3) & 1) * 8 + (lane & 7)) * SAW
                   + (lane >> 4) * 4)) * 4;
#pragma unroll
    for (int jj = 0; jj < 2; jj++)
        bBase[jj] = (u32)((wn + jj * 16 + ((lane >> 4) & 1) * 8 + (lane & 7)) * SAW
                   + ((lane >> 3) & 1) * 4) * 4;

    // prefetch A tile + first B tile in one group
    {
        const u32* srcA = d_z_h + (size_t)rowBase * 64;
#pragma unroll
        for (int i = 0; i < 8; i++) {
            int idx = tid + i * 256;
            int r = idx >> 4, seg = idx & 15;
            cp16(smb + (u32)(r * (SAH * 2) + seg * 16), srcA + r * 64 + seg * 4);
        }
        const u32* srcB = d_emb_h + (size_t)colOrg * 64;
#pragma unroll
        for (int i = 0; i < 8; i++) {
            int idx = tid + i * 256;
            int r = idx >> 4, seg = idx & 15;
            cp16(bsOff + (u32)(r * (SAH * 2) + seg * 16), srcB + r * 64 + seg * 4);
        }
        asm volatile("cp.async.commit_group;" ::: "memory");
    }

    if (tid < 128) {
        zsmem[tid] = d_zsq[rowBase + tid];
        sbest[tid] = ~0ULL;
    }
    __syncthreads();

    float zrow[4][2];
#pragma unroll
    for (int i = 0; i < 4; i++) {
        zrow[i][0] = zsmem[wm + i * 16 + lr];
        zrow[i][1] = zsmem[wm + i * 16 + lr + 8];
    }

    u64 best1[4][2], best2[4][2];
#pragma unroll
    for (int i = 0; i < 4; i++)
#pragma unroll
        for (int s = 0; s < 2; s++) { best1[i][s] = ~0ULL; best2[i][s] = ~0ULL; }

    u32 accA[4][4][2], accB[4][4][2];
    float eqP[4][2];
    int colP = 0;
    bool haveP = false;

#pragma unroll 1
    for (int t2 = 0; t2 < NT_LOCAL / 2; t2++) {
        TILE_BODY(accA, accB, 2 * t2);
        TILE_BODY(accB, accA, 2 * t2 + 1);
    }
#pragma unroll
    for (int p = 0; p < 16; p++) EPI_PAIR(accB, (p >> 2), (p & 3));

    // candidates: this CTA owns 32 slots/row at offset nchunk*32
    const int slot = (wid >> 1) * 4 + lc;             // 0..15 per row
#pragma unroll
    for (int i = 0; i < 4; i++)
#pragma unroll
        for (int s = 0; s < 2; s++) {
            int rl = wm + i * 16 + lr + s * 8;
            atomicMin(&sbest[rl], best1[i][s]);
            u64* c = &d_cand[(size_t)(rowBase + rl) * 128 + nchunk * 32 + slot * 2];
            c[0] = best1[i][s];
            c[1] = best2[i][s];
        }
    __syncthreads();
    if (tid < 128) atomicMin(&d_minkey[rowBase + tid], sbest[tid]);
}

// ---------- fused rescore + gather + sums + counts + finale ----------
__global__ void k_rg(const float* __restrict__ z, const float* __restrict__ emb,
                     float* __restrict__ out, int n_rows) {
    __shared__ float red[8];
    __shared__ u32 s_last;
    const int w = threadIdx.x >> 5;
    const int lane = threadIdx.x & 31;
    const int r = blockIdx.x * 8 + w;

    u64 mk = d_minkey[r];
    float dmin = unfkey((u32)(mk >> 13));
    u32 thr = fkey(dmin + DELTA);

    u64 mykey = ~0ULL;
#pragma unroll
    for (int it = 0; it < 4; it++) {
        u64 key = d_cand[(size_t)r * 128 + lane + it * 32];
        if ((u32)(key >> 13) <= thr) {
            int idx = (int)(key & 0x1FFFULL);
            const float4* zr = (const float4*)(z + (size_t)r * EDIM);
            const float4* er = (const float4*)(emb + (size_t)idx * EDIM);
            float dot = 0.f;
#pragma unroll
            for (int q = 0; q < 32; q++) {
                float4 a = zr[q], b = er[q];
                dot += a.x * b.x + a.y * b.y + a.z * b.z + a.w * b.w;
            }
            float tt = d_zsq[r] + d_esq[idx];         // fl(zsq+esq)
            float d = tt - 2.f * dot;                 // fl(t - 2*dot): grid-exact
            u64 k2 = ((u64)fkey(d) << 13) | (u32)idx;
            if (k2 < mykey) mykey = k2;
        }
    }
#pragma unroll
    for (int off = 16; off; off >>= 1) {
        u64 o = __shfl_xor_sync(0xffffffffu, mykey, off);
        if (o < mykey) mykey = o;
    }
    const int idx = (int)(mykey & 0x1FFFULL);

    float4 q  = ((const float4*)(emb + (size_t)idx * EDIM))[lane];
    float4 zz = ((const float4*)(z   + (size_t)r   * EDIM))[lane];
    float4 o4;
    float s = 0.f, df;
    df = q.x - zz.x; o4.x = zz.x + df; s += df * df;
    df = q.y - zz.y; o4.y = zz.y + df; s += df * df;
    df = q.z - zz.z; o4.z = zz.z + df; s += df * df;
    df = q.w - zz.w; o4.w = zz.w + df; s += df * df;
    ((float4*)(out + (size_t)r * EDIM))[lane] = o4;
#pragma unroll
    for (int off = 16; off; off >>= 1) s += __shfl_xor_sync(0xffffffffu, s, off);
    if (lane == 0) {
        atomicAdd(&d_counts[idx], 1);
        red[w] = s;
    }
    __syncthreads();
    if (threadIdx.x == 0) {
        float bs = 0.f;
#pragma unroll
        for (int i = 0; i < 8; i++) bs += red[i];
        atomicAdd(&d_sumsq, (double)bs);
        __threadfence();
        s_last = (atomicAdd(&d_rgdone, 1u) == gridDim.x - 1u) ? 1u : 0u;
    }
    __syncthreads();

    if (s_last) {
        __threadfence();
        float acc = 0.f;
        float invN = 1.f / (float)n_rows;
        for (int k = threadIdx.x; k < K_CODES; k += 256) {
            float e = (float)d_counts[k] * invN;
            acc += e * logf(e + 1e-8f);
        }
#pragma unroll
        for (int off = 16; off; off >>= 1) acc += __shfl_xor_sync(0xffffffffu, acc, off);
        if (lane == 0) red[w] = acc;
        __syncthreads();
        if (threadIdx.x == 0) {
            float t = 0.f;
#pragma unroll
            for (int i = 0; i < 8; i++) t += red[i];
            double ss = atomicAdd(&d_sumsq, 0.0);
            float m = (float)(ss / (double)((size_t)n_rows * EDIM));
            out[(size_t)n_rows * EDIM]     = 0.25f * m + m;
            out[(size_t)n_rows * EDIM + 1] = expf(-t);
        }
    }
}

extern "C" void kernel_launch(void* const* d_in, const int* in_sizes, int n_in,
                              void* d_out, int out_size) {
    const float* z   = (const float*)d_in[0];
    const float* emb = (const float*)d_in[1];
    float* out = (float*)d_out;
    int n_rows = in_sizes[0] / EDIM;                  // 32768

    cudaFuncSetAttribute(k_main, cudaFuncAttributeMaxDynamicSharedMemorySize, SMEM_TOTAL);

    k_init<<<1280, 256>>>(z, emb);
    k_main<<<(n_rows / TM) * 4, 256, SMEM_TOTAL>>>(z, emb);
    k_rg<<<n_rows / 8, 256>>>(z, emb, out, n_rows);
}

// round 16
// speedup vs baseline: 1.1197x; 1.0115x over previous
#include <cuda_runtime.h>
#include <cuda_fp16.h>

typedef unsigned long long u64;
typedef unsigned int u32;

#define K_CODES 8192
#define EDIM 128
#define TM 128
#define TN 128
#define NCHUNK 2048               // codes per CTA
#define NT_LOCAL (NCHUNK / TN)    // 16 inner tiles
#define SAH 136                   // padded row stride (halfs)
#define SAW 68                    // row stride in 32-bit words
#define A_BYTES (128 * SAH * 2)   // 34816
#define STAGE_BYTES (128 * SAH * 2)
#define ZS_OFF (3 * A_BYTES)                 // float[128]
#define SB_OFF (ZS_OFF + 512)                // u64[128]
#define SMEM_TOTAL (120 * 1024)              // pin 1 CTA/SM
#define DELTA 3e-3f
#define N_ROWS 32768

__device__ float  d_esq[K_CODES];
__device__ float  d_zsq[N_ROWS];
__device__ __align__(16) u32 d_emb_h[K_CODES * 64];   // fp16 image of emb
__device__ __align__(16) u32 d_z_h[N_ROWS * 64];      // fp16 image of z
__device__ int    d_counts[K_CODES];
__device__ u64    d_minkey[N_ROWS];
__device__ u64    d_cand[N_ROWS * 128];
__device__ double d_sumsq;
__device__ u32    d_rgdone;

// ---------------- helpers ----------------
__device__ __forceinline__ u32 smem_u32(const void* p) {
    u32 a; asm("{ .reg .u64 t; cvta.to.shared.u64 t, %1; cvt.u32.u64 %0, t; }" : "=r"(a) : "l"(p));
    return a;
}
__device__ __forceinline__ u32 fkey(float s) {
    u32 b = __float_as_uint(s);
    return (b & 0x80000000u) ? ~b : (b | 0x80000000u);
}
__device__ __forceinline__ float unfkey(u32 k) {
    u32 b = (k & 0x80000000u) ? (k & 0x7FFFFFFFu) : ~k;
    return __uint_as_float(b);
}
__device__ __forceinline__ void cp16(u32 dst, const void* src) {
    asm volatile("cp.async.cg.shared.global [%0], [%1], 16;" :: "r"(dst), "l"(src) : "memory");
}
__device__ __forceinline__ void mma16h(u32* c, const u32* a, const u32* b) {
    asm volatile(
        "mma.sync.aligned.m16n8k16.row.col.f16.f16.f16.f16 "
        "{%0,%1}, {%2,%3,%4,%5}, {%6,%7}, {%0,%1};"
        : "+r"(c[0]), "+r"(c[1])
        : "r"(a[0]), "r"(a[1]), "r"(a[2]), "r"(a[3]), "r"(b[0]), "r"(b[1]));
}
__device__ __forceinline__ void ldsm4(u32* r, u32 addr) {
    asm volatile("ldmatrix.sync.aligned.m8n8.x4.shared.b16 {%0,%1,%2,%3}, [%4];"
        : "=r"(r[0]), "=r"(r[1]), "=r"(r[2]), "=r"(r[3]) : "r"(addr));
}
__device__ __forceinline__ u32 h2u(float x, float y) {
    __half2 h = __floats2half2_rn(x, y);
    return *(u32*)&h;
}
__device__ __forceinline__ void top2(u64& b1, u64& b2, u64 k) {
    if (k < b1) { b2 = b1; b1 = k; }
    else if (k < b2) { b2 = k; }
}

// ---------- kernel 0: fp16 images + zsq/esq (16 threads/row) ----------
__global__ void k_init(const float* __restrict__ z, const float* __restrict__ emb) {
    int idx = blockIdx.x * blockDim.x + threadIdx.x;  // 0..655359
    if (idx < 524288) {                               // z: 32768 rows x 16 threads
        int row = idx >> 4, part = idx & 15;
        const float4* src = (const float4*)(z + (size_t)row * EDIM) + part * 2;
        u32* dst = d_z_h + row * 64 + part * 4;
        float s = 0.f;
#pragma unroll
        for (int i = 0; i < 2; i++) {
            float4 v = src[i];
            s += v.x * v.x + v.y * v.y + v.z * v.z + v.w * v.w;
            dst[i * 2]     = h2u(v.x, v.y);
            dst[i * 2 + 1] = h2u(v.z, v.w);
        }
        s += __shfl_xor_sync(0xffffffffu, s, 1);
        s += __shfl_xor_sync(0xffffffffu, s, 2);
        s += __shfl_xor_sync(0xffffffffu, s, 4);
        s += __shfl_xor_sync(0xffffffffu, s, 8);
        if (part == 0) { d_zsq[row] = s; d_minkey[row] = ~0ULL; }
    } else {                                          // emb: 8192 rows x 16 threads
        int e = idx - 524288;
        int row = e >> 4, part = e & 15;
        const float4* src = (const float4*)(emb + (size_t)row * EDIM) + part * 2;
        u32* dst = d_emb_h + row * 64 + part * 4;
        float s = 0.f;
#pragma unroll
        for (int i = 0; i < 2; i++) {
            float4 v = src[i];
            s += v.x * v.x + v.y * v.y + v.z * v.z + v.w * v.w;
            dst[i * 2]     = h2u(v.x, v.y);
            dst[i * 2 + 1] = h2u(v.z, v.w);
        }
        s += __shfl_xor_sync(0xffffffffu, s, 1);
        s += __shfl_xor_sync(0xffffffffu, s, 2);
        s += __shfl_xor_sync(0xffffffffu, s, 4);
        s += __shfl_xor_sync(0xffffffffu, s, 8);
        if (part == 0) { d_esq[row] = s; d_counts[row] = 0; }
    }
    if (idx == 0) { d_sumsq = 0.0; d_rgdone = 0; }
}

// epilogue of one (i,j) fragment pair (grid-exact formula, top-2)
#define EPI_PAIR(ACC, I, J) do {                                              \
    int _cg0 = colP + wn + (J) * 8 + 2 * lc;                                  \
    float2 _g0 = __half22float2(*(__half2*)&ACC[I][J][0]);                    \
    float2 _g1 = __half22float2(*(__half2*)&ACC[I][J][1]);                    \
    float _d0 = (zrow[I][0] + eqP[J][0]) - 2.f * _g0.x;                       \
    float _d1 = (zrow[I][0] + eqP[J][1]) - 2.f * _g0.y;                       \
    top2(best1[I][0], best2[I][0], ((u64)fkey(_d0) << 13) | (u32)_cg0);       \
    top2(best1[I][0], best2[I][0], ((u64)fkey(_d1) << 13) | (u32)(_cg0 + 1)); \
    float _e0 = (zrow[I][1] + eqP[J][0]) - 2.f * _g1.x;                       \
    float _e1 = (zrow[I][1] + eqP[J][1]) - 2.f * _g1.y;                       \
    top2(best1[I][1], best2[I][1], ((u64)fkey(_e0) << 13) | (u32)_cg0);       \
    top2(best1[I][1], best2[I][1], ((u64)fkey(_e1) << 13) | (u32)(_cg0 + 1)); \
} while (0)

// one tile: wait data -> single sync -> issue next prefetch -> mma (+ prev epi)
#define TILE_BODY(ACC, ACCP, TILE) do {                                       \
    const int colBase = colOrg + (TILE) * TN;                                 \
    float eqC[4][2];                                                          \
    _Pragma("unroll") for (int j = 0; j < 4; j++) {                           \
        int c0 = colBase + wn + j * 8 + 2 * lc;                               \
        eqC[j][0] = d_esq[c0]; eqC[j][1] = d_esq[c0 + 1];                     \
    }                                                                         \
    asm volatile("cp.async.wait_group 0;" ::: "memory");                      \
    __syncthreads();                                                          \
    if ((TILE) + 1 < NT_LOCAL) {                                              \
        const u32* src = d_emb_h + (size_t)(colBase + TN) * 64;               \
        u32 dstb = bsOff + (((TILE) + 1) & 1) * STAGE_BYTES;                  \
        _Pragma("unroll") for (int i = 0; i < 8; i++) {                       \
            int idx = tid + i * 256; int r = idx >> 4, seg = idx & 15;        \
            cp16(dstb + (u32)(r * (SAH * 2) + seg * 16), src + r * 64 + seg * 4); \
        }                                                                     \
        asm volatile("cp.async.commit_group;" ::: "memory");                  \
    }                                                                         \
    const u32 bSt = bsOff + ((TILE) & 1) * STAGE_BYTES;                       \
    _Pragma("unroll") for (int i = 0; i < 4; i++)                             \
        _Pragma("unroll") for (int j = 0; j < 4; j++) {                       \
            ACC[i][j][0] = 0u; ACC[i][j][1] = 0u;                             \
        }                                                                     \
    _Pragma("unroll") for (int kb = 0; kb < 8; kb++) {                        \
        const u32 kOff = (u32)kb * 32;                                        \
        u32 af[4][4], bf[2][4];                                               \
        _Pragma("unroll") for (int i = 0; i < 4; i++) ldsm4(af[i], aBase[i] + kOff); \
        _Pragma("unroll") for (int jj = 0; jj < 2; jj++) ldsm4(bf[jj], bSt + bBase[jj] + kOff); \
        _Pragma("unroll") for (int i = 0; i < 4; i++) {                       \
            mma16h(ACC[i][0], af[i], &bf[0][0]);                              \
            mma16h(ACC[i][1], af[i], &bf[0][2]);                              \
            mma16h(ACC[i][2], af[i], &bf[1][0]);                              \
            mma16h(ACC[i][3], af[i], &bf[1][2]);                              \
        }                                                                     \
        if (haveP) {                                                          \
            EPI_PAIR(ACCP, (kb >> 1), ((2 * kb) & 3));                        \
            EPI_PAIR(ACCP, (kb >> 1), ((2 * kb + 1) & 3));                    \
        }                                                                     \
    }                                                                         \
    _Pragma("unroll") for (int j = 0; j < 4; j++) {                           \
        eqP[j][0] = eqC[j][0]; eqP[j][1] = eqC[j][1];                         \
    }                                                                         \
    colP = colBase; haveP = true;                                             \
} while (0)

// ---------- main: fp16 screening GEMM, N-split x4, pipelined epilogue ----------
extern "C" __global__ void __launch_bounds__(256, 1)
k_main(const float* __restrict__ z, const float* __restrict__ emb) {
    extern __shared__ char smem[];
    float* zsmem = (float*)(smem + ZS_OFF);           // [128]
    u64*   sbest = (u64*)(smem + SB_OFF);             // [128]

    const int tid  = threadIdx.x;
    const int wid  = tid >> 5;
    const int lane = tid & 31;
    const int lr   = lane >> 2;
    const int lc   = lane & 3;
    const int wm   = (wid & 1) * 64;
    const int wn   = (wid >> 1) * 32;
    const int rowBase = (blockIdx.x >> 2) * TM;
    const int nchunk  = blockIdx.x & 3;
    const int colOrg  = nchunk * NCHUNK;

    const u32 smb   = smem_u32(smem);
    const u32 bsOff = smb + A_BYTES;

    u32 aBase[4], bBase[2];
#pragma unroll
    for (int i = 0; i < 4; i++)
        aBase[i] = smb + ((u32)((wm + i * 16 + ((lane >> 3) & 1) * 8 + (lane & 7)) * SAW
                   + (lane >> 4) * 4)) * 4;
#pragma unroll
    for (int jj = 0; jj < 2; jj++)
        bBase[jj] = (u32)((wn + jj * 16 + ((lane >> 4) & 1) * 8 + (lane & 7)) * SAW
                   + ((lane >> 3) & 1) * 4) * 4;

    // prefetch A tile + first B tile in one group
    {
        const u32* srcA = d_z_h + (size_t)rowBase * 64;
#pragma unroll
        for (int i = 0; i < 8; i++) {
            int idx = tid + i * 256;
            int r = idx >> 4, seg = idx & 15;
            cp16(smb + (u32)(r * (SAH * 2) + seg * 16), srcA + r * 64 + seg * 4);
        }
        const u32* srcB = d_emb_h + (size_t)colOrg * 64;
#pragma unroll
        for (int i = 0; i < 8; i++) {
            int idx = tid + i * 256;
            int r = idx >> 4, seg = idx & 15;
            cp16(bsOff + (u32)(r * (SAH * 2) + seg * 16), srcB + r * 64 + seg * 4);
        }
        asm volatile("cp.async.commit_group;" ::: "memory");
    }

    if (tid < 128) {
        zsmem[tid] = d_zsq[rowBase + tid];
        sbest[tid] = ~0ULL;
    }
    __syncthreads();

    float zrow[4][2];
#pragma unroll
    for (int i = 0; i < 4; i++) {
        zrow[i][0] = zsmem[wm + i * 16 + lr];
        zrow[i][1] = zsmem[wm + i * 16 + lr + 8];
    }

    u64 best1[4][2], best2[4][2];
#pragma unroll
    for (int i = 0; i < 4; i++)
#pragma unroll
        for (int s = 0; s < 2; s++) { best1[i][s] = ~0ULL; best2[i][s] = ~0ULL; }

    u32 accA[4][4][2], accB[4][4][2];
    float eqP[4][2];
    int colP = 0;
    bool haveP = false;

#pragma unroll 1
    for (int t2 = 0; t2 < NT_LOCAL / 2; t2++) {
        TILE_BODY(accA, accB, 2 * t2);
        TILE_BODY(accB, accA, 2 * t2 + 1);
    }
#pragma unroll
    for (int p = 0; p < 16; p++) EPI_PAIR(accB, (p >> 2), (p & 3));

    // candidates: this CTA owns 32 slots/row at offset nchunk*32
    const int slot = (wid >> 1) * 4 + lc;             // 0..15 per row
#pragma unroll
    for (int i = 0; i < 4; i++)
#pragma unroll
        for (int s = 0; s < 2; s++) {
            int rl = wm + i * 16 + lr + s * 8;
            atomicMin(&sbest[rl], best1[i][s]);
            u64* c = &d_cand[(size_t)(rowBase + rl) * 128 + nchunk * 32 + slot * 2];
            c[0] = best1[i][s];
            c[1] = best2[i][s];
        }
    __syncthreads();
    if (tid < 128) atomicMin(&d_minkey[rowBase + tid], sbest[tid]);
}

// ---------- fused rescore + gather + sums + counts + finale ----------
__global__ void k_rg(const float* __restrict__ z, const float* __restrict__ emb,
                     float* __restrict__ out, int n_rows) {
    __shared__ float red[8];
    __shared__ u32 s_last;
    const int w = threadIdx.x >> 5;
    const int lane = threadIdx.x & 31;
    const int r = blockIdx.x * 8 + w;

    u64 mk = d_minkey[r];
    float dmin = unfkey((u32)(mk >> 13));
    u32 thr = fkey(dmin + DELTA);

    u64 mykey = ~0ULL;
#pragma unroll
    for (int it = 0; it < 4; it++) {
        u64 key = d_cand[(size_t)r * 128 + lane + it * 32];
        if ((u32)(key >> 13) <= thr) {
            int idx = (int)(key & 0x1FFFULL);
            const float4* zr = (const float4*)(z + (size_t)r * EDIM);
            const float4* er = (const float4*)(emb + (size_t)idx * EDIM);
            float dot = 0.f;
#pragma unroll
            for (int q = 0; q < 32; q++) {
                float4 a = zr[q], b = er[q];
                dot += a.x * b.x + a.y * b.y + a.z * b.z + a.w * b.w;
            }
            float tt = d_zsq[r] + d_esq[idx];         // fl(zsq+esq)
            float d = tt - 2.f * dot;                 // fl(t - 2*dot): grid-exact
            u64 k2 = ((u64)fkey(d) << 13) | (u32)idx;
            if (k2 < mykey) mykey = k2;
        }
    }
#pragma unroll
    for (int off = 16; off; off >>= 1) {
        u64 o = __shfl_xor_sync(0xffffffffu, mykey, off);
        if (o < mykey) mykey = o;
    }
    const int idx = (int)(mykey & 0x1FFFULL);

    float4 q  = ((const float4*)(emb + (size_t)idx * EDIM))[lane];
    float4 zz = ((const float4*)(z   + (size_t)r   * EDIM))[lane];
    float4 o4;
    float s = 0.f, df;
    df = q.x - zz.x; o4.x = zz.x + df; s += df * df;
    df = q.y - zz.y; o4.y = zz.y + df; s += df * df;
    df = q.z - zz.z; o4.z = zz.z + df; s += df * df;
    df = q.w - zz.w; o4.w = zz.w + df; s += df * df;
    ((float4*)(out + (size_t)r * EDIM))[lane] = o4;
#pragma unroll
    for (int off = 16; off; off >>= 1) s += __shfl_xor_sync(0xffffffffu, s, off);
    if (lane == 0) {
        atomicAdd(&d_counts[idx], 1);
        red[w] = s;
    }
    __syncthreads();
    if (threadIdx.x == 0) {
        float bs = 0.f;
#pragma unroll
        for (int i = 0; i < 8; i++) bs += red[i];
        atomicAdd(&d_sumsq, (double)bs);
        __threadfence();
        s_last = (atomicAdd(&d_rgdone, 1u) == gridDim.x - 1u) ? 1u : 0u;
    }
    __syncthreads();

    if (s_last) {
        __threadfence();
        float acc = 0.f;
        float invN = 1.f / (float)n_rows;
        for (int k = threadIdx.x; k < K_CODES; k += 256) {
            float e = (float)d_counts[k] * invN;
            acc += e * logf(e + 1e-8f);
        }
#pragma unroll
        for (int off = 16; off; off >>= 1) acc += __shfl_xor_sync(0xffffffffu, acc, off);
        if (lane == 0) red[w] = acc;
        __syncthreads();
        if (threadIdx.x == 0) {
            float t = 0.f;
#pragma unroll
            for (int i = 0; i < 8; i++) t += red[i];
            double ss = atomicAdd(&d_sumsq, 0.0);
            float m = (float)(ss / (double)((size_t)n_rows * EDIM));
            out[(size_t)n_rows * EDIM]     = 0.25f * m + m;
            out[(size_t)n_rows * EDIM + 1] = expf(-t);
        }
    }
}

extern "C" void kernel_launch(void* const* d_in, const int* in_sizes, int n_in,
                              void* d_out, int out_size) {
    const float* z   = (const float*)d_in[0];
    const float* emb = (const float*)d_in[1];
    float* out = (float*)d_out;
    int n_rows = in_sizes[0] / EDIM;                  // 32768

    cudaFuncSetAttribute(k_main, cudaFuncAttributeMaxDynamicSharedMemorySize, SMEM_TOTAL);

    k_init<<<2560, 256>>>(z, emb);
    k_main<<<(n_rows / TM) * 4, 256, SMEM_TOTAL>>>(z, emb);
    k_rg<<<n_rows / 8, 256>>>(z, emb, out, n_rows);
}

// round 17
// speedup vs baseline: 1.2070x; 1.0780x over previous
#include <cuda_runtime.h>
#include <cuda_fp16.h>

typedef unsigned long long u64;
typedef unsigned int u32;

#define K_CODES 8192
#define EDIM 128
#define TM 128
#define TN 128
#define NCHUNK 2048               // codes per CTA
#define NT_LOCAL (NCHUNK / TN)    // 16 inner tiles
#define SAH 136                   // padded row stride (halfs)
#define SAW 68                    // row stride in 32-bit words
#define A_BYTES (128 * SAH * 2)   // 34816
#define STAGE_BYTES (128 * SAH * 2)
#define ZS_OFF (3 * A_BYTES)                 // float[128]
#define SB_OFF (ZS_OFF + 512)                // u64[128]
#define SMEM_TOTAL (120 * 1024)              // pin 1 CTA/SM
#define DELTA 3e-3f
#define N_ROWS 32768

__device__ float  d_esq[K_CODES];
__device__ float  d_zsq[N_ROWS];
__device__ __align__(16) u32 d_emb_h[K_CODES * 64];   // fp16 image of emb
__device__ __align__(16) u32 d_z_h[N_ROWS * 64];      // fp16 image of z
__device__ int    d_counts[K_CODES];
__device__ u64    d_minkey[N_ROWS];
__device__ u64    d_cand[N_ROWS * 128];
__device__ double d_sumsq;
__device__ u32    d_rgdone;

// ---------------- helpers ----------------
__device__ __forceinline__ u32 smem_u32(const void* p) {
    u32 a; asm("{ .reg .u64 t; cvta.to.shared.u64 t, %1; cvt.u32.u64 %0, t; }" : "=r"(a) : "l"(p));
    return a;
}
__device__ __forceinline__ u32 fkey(float s) {
    u32 b = __float_as_uint(s);
    return (b & 0x80000000u) ? ~b : (b | 0x80000000u);
}
__device__ __forceinline__ float unfkey(u32 k) {
    u32 b = (k & 0x80000000u) ? (k & 0x7FFFFFFFu) : ~k;
    return __uint_as_float(b);
}
__device__ __forceinline__ void cp16(u32 dst, const void* src) {
    asm volatile("cp.async.cg.shared.global [%0], [%1], 16;" :: "r"(dst), "l"(src) : "memory");
}
__device__ __forceinline__ void mma16h(u32* c, const u32* a, const u32* b) {
    asm volatile(
        "mma.sync.aligned.m16n8k16.row.col.f16.f16.f16.f16 "
        "{%0,%1}, {%2,%3,%4,%5}, {%6,%7}, {%0,%1};"
        : "+r"(c[0]), "+r"(c[1])
        : "r"(a[0]), "r"(a[1]), "r"(a[2]), "r"(a[3]), "r"(b[0]), "r"(b[1]));
}
__device__ __forceinline__ void ldsm4(u32* r, u32 addr) {
    asm volatile("ldmatrix.sync.aligned.m8n8.x4.shared.b16 {%0,%1,%2,%3}, [%4];"
        : "=r"(r[0]), "=r"(r[1]), "=r"(r[2]), "=r"(r[3]) : "r"(addr));
}
__device__ __forceinline__ u32 h2u(float x, float y) {
    __half2 h = __floats2half2_rn(x, y);
    return *(u32*)&h;
}
__device__ __forceinline__ void top2(u64& b1, u64& b2, u64 k) {
    if (k < b1) { b2 = b1; b1 = k; }
    else if (k < b2) { b2 = k; }
}

// ---------- kernel 0: fp16 images + zsq/esq (16 threads/row) ----------
__global__ void k_init(const float* __restrict__ z, const float* __restrict__ emb) {
    int idx = blockIdx.x * blockDim.x + threadIdx.x;  // 0..655359
    if (idx < 524288) {                               // z: 32768 rows x 16 threads
        int row = idx >> 4, part = idx & 15;
        const float4* src = (const float4*)(z + (size_t)row * EDIM) + part * 2;
        u32* dst = d_z_h + row * 64 + part * 4;
        float s = 0.f;
#pragma unroll
        for (int i = 0; i < 2; i++) {
            float4 v = src[i];
            s += v.x * v.x + v.y * v.y + v.z * v.z + v.w * v.w;
            dst[i * 2]     = h2u(v.x, v.y);
            dst[i * 2 + 1] = h2u(v.z, v.w);
        }
        s += __shfl_xor_sync(0xffffffffu, s, 1);
        s += __shfl_xor_sync(0xffffffffu, s, 2);
        s += __shfl_xor_sync(0xffffffffu, s, 4);
        s += __shfl_xor_sync(0xffffffffu, s, 8);
        if (part == 0) { d_zsq[row] = s; d_minkey[row] = ~0ULL; }
    } else {                                          // emb: 8192 rows x 16 threads
        int e = idx - 524288;
        int row = e >> 4, part = e & 15;
        const float4* src = (const float4*)(emb + (size_t)row * EDIM) + part * 2;
        u32* dst = d_emb_h + row * 64 + part * 4;
        float s = 0.f;
#pragma unroll
        for (int i = 0; i < 2; i++) {
            float4 v = src[i];
            s += v.x * v.x + v.y * v.y + v.z * v.z + v.w * v.w;
            dst[i * 2]     = h2u(v.x, v.y);
            dst[i * 2 + 1] = h2u(v.z, v.w);
        }
        s += __shfl_xor_sync(0xffffffffu, s, 1);
        s += __shfl_xor_sync(0xffffffffu, s, 2);
        s += __shfl_xor_sync(0xffffffffu, s, 4);
        s += __shfl_xor_sync(0xffffffffu, s, 8);
        if (part == 0) { d_esq[row] = s; d_counts[row] = 0; }
    }
    if (idx == 0) { d_sumsq = 0.0; d_rgdone = 0; }
}

// epilogue of one (i,j) fragment pair (grid-exact formula, top-2)
#define EPI_PAIR(ACC, I, J) do {                                              \
    int _cg0 = colP + wn + (J) * 8 + 2 * lc;                                  \
    float2 _g0 = __half22float2(*(__half2*)&ACC[I][J][0]);                    \
    float2 _g1 = __half22float2(*(__half2*)&ACC[I][J][1]);                    \
    float _d0 = (zrow[I][0] + eqP[J][0]) - 2.f * _g0.x;                       \
    float _d1 = (zrow[I][0] + eqP[J][1]) - 2.f * _g0.y;                       \
    top2(best1[I][0], best2[I][0], ((u64)fkey(_d0) << 13) | (u32)_cg0);       \
    top2(best1[I][0], best2[I][0], ((u64)fkey(_d1) << 13) | (u32)(_cg0 + 1)); \
    float _e0 = (zrow[I][1] + eqP[J][0]) - 2.f * _g1.x;                       \
    float _e1 = (zrow[I][1] + eqP[J][1]) - 2.f * _g1.y;                       \
    top2(best1[I][1], best2[I][1], ((u64)fkey(_e0) << 13) | (u32)_cg0);       \
    top2(best1[I][1], best2[I][1], ((u64)fkey(_e1) << 13) | (u32)(_cg0 + 1)); \
} while (0)

// one tile: wait data -> single sync -> issue next prefetch -> mma (+ prev epi)
#define TILE_BODY(ACC, ACCP, TILE) do {                                       \
    const int colBase = colOrg + (TILE) * TN;                                 \
    float eqC[4][2];                                                          \
    _Pragma("unroll") for (int j = 0; j < 4; j++) {                           \
        int c0 = colBase + wn + j * 8 + 2 * lc;                               \
        eqC[j][0] = d_esq[c0]; eqC[j][1] = d_esq[c0 + 1];                     \
    }                                                                         \
    asm volatile("cp.async.wait_group 0;" ::: "memory");                      \
    __syncthreads();                                                          \
    if ((TILE) + 1 < NT_LOCAL) {                                              \
        const u32* src = d_emb_h + (size_t)(colBase + TN) * 64;               \
        u32 dstb = bsOff + (((TILE) + 1) & 1) * STAGE_BYTES;                  \
        _Pragma("unroll") for (int i = 0; i < 8; i++) {                       \
            int idx = tid + i * 256; int r = idx >> 4, seg = idx & 15;        \
            cp16(dstb + (u32)(r * (SAH * 2) + seg * 16), src + r * 64 + seg * 4); \
        }                                                                     \
        asm volatile("cp.async.commit_group;" ::: "memory");                  \
    }                                                                         \
    const u32 bSt = bsOff + ((TILE) & 1) * STAGE_BYTES;                       \
    _Pragma("unroll") for (int i = 0; i < 4; i++)                             \
        _Pragma("unroll") for (int j = 0; j < 4; j++) {                       \
            ACC[i][j][0] = 0u; ACC[i][j][1] = 0u;                             \
        }                                                                     \
    _Pragma("unroll") for (int kb = 0; kb < 8; kb++) {                        \
        const u32 kOff = (u32)kb * 32;                                        \
        u32 af[4][4], bf[2][4];                                               \
        _Pragma("unroll") for (int i = 0; i < 4; i++) ldsm4(af[i], aBase[i] + kOff); \
        _Pragma("unroll") for (int jj = 0; jj < 2; jj++) ldsm4(bf[jj], bSt + bBase[jj] + kOff); \
        _Pragma("unroll") for (int i = 0; i < 4; i++) {                       \
            mma16h(ACC[i][0], af[i], &bf[0][0]);                              \
            mma16h(ACC[i][1], af[i], &bf[0][2]);                              \
            mma16h(ACC[i][2], af[i], &bf[1][0]);                              \
            mma16h(ACC[i][3], af[i], &bf[1][2]);                              \
        }                                                                     \
        if (haveP) {                                                          \
            EPI_PAIR(ACCP, (kb >> 1), ((2 * kb) & 3));                        \
            EPI_PAIR(ACCP, (kb >> 1), ((2 * kb + 1) & 3));                    \
        }                                                                     \
    }                                                                         \
    _Pragma("unroll") for (int j = 0; j < 4; j++) {                           \
        eqP[j][0] = eqC[j][0]; eqP[j][1] = eqC[j][1];                         \
    }                                                                         \
    colP = colBase; haveP = true;                                             \
} while (0)

// ---------- main: fp16 screening GEMM, N-split x4, pipelined epilogue ----------
extern "C" __global__ void __launch_bounds__(256, 1)
k_main(const float* __restrict__ z, const float* __restrict__ emb) {
    extern __shared__ char smem[];
    float* zsmem = (float*)(smem + ZS_OFF);           // [128]
    u64*   sbest = (u64*)(smem + SB_OFF);             // [128]

    const int tid  = threadIdx.x;
    const int wid  = tid >> 5;
    const int lane = tid & 31;
    const int lr   = lane >> 2;
    const int lc   = lane & 3;
    const int wm   = (wid & 1) * 64;
    const int wn   = (wid >> 1) * 32;
    const int rowBase = (blockIdx.x >> 2) * TM;
    const int nchunk  = blockIdx.x & 3;
    const int colOrg  = nchunk * NCHUNK;

    const u32 smb   = smem_u32(smem);
    const u32 bsOff = smb + A_BYTES;

    u32 aBase[4], bBase[2];
#pragma unroll
    for (int i = 0; i < 4; i++)
        aBase[i] = smb + ((u32)((wm + i * 16 + ((lane >> 3) & 1) * 8 + (lane & 7)) * SAW
                   + (lane >> 4) * 4)) * 4;
#pragma unroll
    for (int jj = 0; jj < 2; jj++)
        bBase[jj] = (u32)((wn + jj * 16 + ((lane >> 4) & 1) * 8 + (lane & 7)) * SAW
                   + ((lane >> 3) & 1) * 4) * 4;

    // prefetch A tile + first B tile in one group
    {
        const u32* srcA = d_z_h + (size_t)rowBase * 64;
#pragma unroll
        for (int i = 0; i < 8; i++) {
            int idx = tid + i * 256;
            int r = idx >> 4, seg = idx & 15;
            cp16(smb + (u32)(r * (SAH * 2) + seg * 16), srcA + r * 64 + seg * 4);
        }
        const u32* srcB = d_emb_h + (size_t)colOrg * 64;
#pragma unroll
        for (int i = 0; i < 8; i++) {
            int idx = tid + i * 256;
            int r = idx >> 4, seg = idx & 15;
            cp16(bsOff + (u32)(r * (SAH * 2) + seg * 16), srcB + r * 64 + seg * 4);
        }
        asm volatile("cp.async.commit_group;" ::: "memory");
    }

    if (tid < 128) {
        zsmem[tid] = d_zsq[rowBase + tid];
        sbest[tid] = ~0ULL;
    }
    __syncthreads();

    float zrow[4][2];
#pragma unroll
    for (int i = 0; i < 4; i++) {
        zrow[i][0] = zsmem[wm + i * 16 + lr];
        zrow[i][1] = zsmem[wm + i * 16 + lr + 8];
    }

    u64 best1[4][2], best2[4][2];
#pragma unroll
    for (int i = 0; i < 4; i++)
#pragma unroll
        for (int s = 0; s < 2; s++) { best1[i][s] = ~0ULL; best2[i][s] = ~0ULL; }

    u32 accA[4][4][2], accB[4][4][2];
    float eqP[4][2];
    int colP = 0;
    bool haveP = false;

#pragma unroll 1
    for (int t2 = 0; t2 < NT_LOCAL / 2; t2++) {
        TILE_BODY(accA, accB, 2 * t2);
        TILE_BODY(accB, accA, 2 * t2 + 1);
    }
#pragma unroll
    for (int p = 0; p < 16; p++) EPI_PAIR(accB, (p >> 2), (p & 3));

    // candidates: this CTA owns 32 slots/row at offset nchunk*32
    const int slot = (wid >> 1) * 4 + lc;             // 0..15 per row
#pragma unroll
    for (int i = 0; i < 4; i++)
#pragma unroll
        for (int s = 0; s < 2; s++) {
            int rl = wm + i * 16 + lr + s * 8;
            atomicMin(&sbest[rl], best1[i][s]);
            u64* c = &d_cand[(size_t)(rowBase + rl) * 128 + nchunk * 32 + slot * 2];
            c[0] = best1[i][s];
            c[1] = best2[i][s];
        }
    __syncthreads();
    if (tid < 128) atomicMin(&d_minkey[rowBase + tid], sbest[tid]);
}

// ---------- fused rescore (warp-cooperative) + gather + finale ----------
__global__ void k_rg(const float* __restrict__ z, const float* __restrict__ emb,
                     float* __restrict__ out, int n_rows) {
    __shared__ float red[8];
    __shared__ u32 s_last;
    const int w = threadIdx.x >> 5;
    const int lane = threadIdx.x & 31;
    const int r = blockIdx.x * 8 + w;

    // z row: one float4 per lane (reused by rescore dot AND gather)
    float4 zz = ((const float4*)(z + (size_t)r * EDIM))[lane];
    float zsq = d_zsq[r];

    u64 mk = d_minkey[r];
    float dmin = unfkey((u32)(mk >> 13));
    u32 thr = fkey(dmin + DELTA);

    u64 mykey = ~0ULL;
#pragma unroll
    for (int it = 0; it < 4; it++) {
        u64 key = d_cand[(size_t)r * 128 + lane + it * 32];
        u32 pass = ((u32)(key >> 13) <= thr) ? 1u : 0u;
        u32 bal = __ballot_sync(0xffffffffu, pass);
        while (bal) {
            int src = __ffs(bal) - 1;
            bal &= bal - 1;
            int idx = (int)(__shfl_sync(0xffffffffu, key, src) & 0x1FFFULL);
            // warp-cooperative exact fp32 dot (order-robust under grid quantization)
            float4 e4 = ((const float4*)(emb + (size_t)idx * EDIM))[lane];
            float p = zz.x * e4.x + zz.y * e4.y + zz.z * e4.z + zz.w * e4.w;
#pragma unroll
            for (int off = 16; off; off >>= 1)
                p += __shfl_xor_sync(0xffffffffu, p, off);
            float tt = zsq + d_esq[idx];              // fl(zsq+esq)
            float d = tt - 2.f * p;                   // fl(t - 2*dot): grid-exact
            u64 k2 = ((u64)fkey(d) << 13) | (u32)idx;
            if (k2 < mykey) mykey = k2;
        }
    }
    // all lanes hold identical mykey (uniform computation)
    const int idx = (int)(mykey & 0x1FFFULL);

    float4 q = ((const float4*)(emb + (size_t)idx * EDIM))[lane];
    float4 o4;
    float s = 0.f, df;
    df = q.x - zz.x; o4.x = zz.x + df; s += df * df;
    df = q.y - zz.y; o4.y = zz.y + df; s += df * df;
    df = q.z - zz.z; o4.z = zz.z + df; s += df * df;
    df = q.w - zz.w; o4.w = zz.w + df; s += df * df;
    ((float4*)(out + (size_t)r * EDIM))[lane] = o4;
#pragma unroll
    for (int off = 16; off; off >>= 1) s += __shfl_xor_sync(0xffffffffu, s, off);
    if (lane == 0) {
        atomicAdd(&d_counts[idx], 1);
        red[w] = s;
    }
    __syncthreads();
    if (threadIdx.x == 0) {
        float bs = 0.f;
#pragma unroll
        for (int i = 0; i < 8; i++) bs += red[i];
        atomicAdd(&d_sumsq, (double)bs);
        __threadfence();
        s_last = (atomicAdd(&d_rgdone, 1u) == gridDim.x - 1u) ? 1u : 0u;
    }
    __syncthreads();

    if (s_last) {
        __threadfence();
        float acc = 0.f;
        float invN = 1.f / (float)n_rows;
        for (int k = threadIdx.x; k < K_CODES; k += 256) {
            float e = (float)d_counts[k] * invN;
            acc += e * logf(e + 1e-8f);
        }
#pragma unroll
        for (int off = 16; off; off >>= 1) acc += __shfl_xor_sync(0xffffffffu, acc, off);
        if (lane == 0) red[w] = acc;
        __syncthreads();
        if (threadIdx.x == 0) {
            float t = 0.f;
#pragma unroll
            for (int i = 0; i < 8; i++) t += red[i];
            double ss = atomicAdd(&d_sumsq, 0.0);
            float m = (float)(ss / (double)((size_t)n_rows * EDIM));
            out[(size_t)n_rows * EDIM]     = 0.25f * m + m;
            out[(size_t)n_rows * EDIM + 1] = expf(-t);
        }
    }
}

extern "C" void kernel_launch(void* const* d_in, const int* in_sizes, int n_in,
                              void* d_out, int out_size) {
    const float* z   = (const float*)d_in[0];
    const float* emb = (const float*)d_in[1];
    float* out = (float*)d_out;
    int n_rows = in_sizes[0] / EDIM;                  // 32768

    cudaFuncSetAttribute(k_main, cudaFuncAttributeMaxDynamicSharedMemorySize, SMEM_TOTAL);

    k_init<<<2560, 256>>>(z, emb);
    k_main<<<(n_rows / TM) * 4, 256, SMEM_TOTAL>>>(z, emb);
    k_rg<<<n_rows / 8, 256>>>(z, emb, out, n_rows);
}